// round 7
// baseline (speedup 1.0000x reference)
#include <cuda_runtime.h>
#include <cstddef>

#define BB   16
#define NN   8192
#define SS   1024        // NPOINT
#define KK   32          // NSAMPLE
#define DD   9
#define MCOL (BB*SS*KK)  // 524288 columns
#define NBLKMAX 4096     // g_ps leading stride
#define NBLK1 4096       // gemm1/2 blocks (128-wide tiles)
#define NBLK0 1024       // gemm0 role blocks (512-wide tiles)

// ---------------- device scratch (static: no cudaMalloc allowed) ----------------
__device__ float  g_X0[(size_t)DD  * MCOL];   // gathered input   (9  x 524288)
__device__ float  g_Y0[(size_t)64  * MCOL];   // layer0 raw out
__device__ float  g_Y1[(size_t)64  * MCOL];   // layer1 raw out
__device__ float  g_P2[(size_t)BB * SS * 128];// layer2 pooled raw max  [ms][c]
__device__ int    g_cent[BB * SS];
__device__ double g_ps [(size_t)128 * NBLKMAX];
__device__ double g_pss[(size_t)128 * NBLKMAX];
__device__ float  g_scl[3][128];
__device__ float  g_shf[3][128];
__device__ int    g_prog[BB];                 // fps progress per batch
__device__ int    g_flag[512];                // ballquery block completion flags

// ---------------- f32x2 packed helpers (sm_100+) ----------------
__device__ __forceinline__ unsigned long long pack2(float a, float b) {
    unsigned long long r;
    asm("mov.b64 %0, {%1, %2};" : "=l"(r) : "f"(a), "f"(b));
    return r;
}
__device__ __forceinline__ void unpack2(unsigned long long v, float& a, float& b) {
    asm("mov.b64 {%0, %1}, %2;" : "=f"(a), "=f"(b) : "l"(v));
}
__device__ __forceinline__ unsigned long long add2(unsigned long long a, unsigned long long b) {
    unsigned long long r;
    asm("add.rn.f32x2 %0, %1, %2;" : "=l"(r) : "l"(a), "l"(b));
    return r;
}
__device__ __forceinline__ unsigned long long mul2(unsigned long long a, unsigned long long b) {
    unsigned long long r;
    asm("mul.rn.f32x2 %0, %1, %2;" : "=l"(r) : "l"(a), "l"(b));
    return r;
}
__device__ __forceinline__ unsigned long long fma2(unsigned long long a, unsigned long long b, unsigned long long c) {
    unsigned long long r;
    asm("fma.rn.f32x2 %0, %1, %2, %3;" : "=l"(r) : "l"(a), "l"(b), "l"(c));
    return r;
}

// ---------------- pads + reset ----------------
__global__ void pad_kernel() {}
__global__ void reset_kernel() {
    int t = threadIdx.x;
    if (t < BB) g_prog[t] = 0;
    for (int i = t; i < 512; i += blockDim.x) g_flag[i] = 0;
}

// ================= role: FPS (bids 0..15) =================
// d = fma(dz,dz, fma(dy,dy, dx*dx)) with dx = x + (-cx)  (== x - cx exactly)
__device__ __forceinline__ void fps_role(const float* __restrict__ xyz, float* sh, int b)
{
    float* sx = sh;
    float* sy = sh + NN;
    float* sz = sh + 2 * NN;
    __shared__ unsigned wmax[2][32];
    __shared__ int sidx[2];

    int t = threadIdx.x;
    int lane = t & 31, w = t >> 5;
    const float* xb = xyz + (size_t)b * NN * 3;

    float xs[8], ys[8], zs[8], Dst[8];
#pragma unroll
    for (int j = 0; j < 8; j++) {
        int p = j * 1024 + t;
        xs[j] = xb[p * 3 + 0];
        ys[j] = xb[p * 3 + 1];
        zs[j] = xb[p * 3 + 2];
        Dst[j] = 1e10f;
        sx[p] = xs[j]; sy[p] = ys[j]; sz[p] = zs[j];
    }
    unsigned long long X2[4], Y2[4], Z2[4];
#pragma unroll
    for (int jp = 0; jp < 4; jp++) {
        X2[jp] = pack2(xs[2 * jp], xs[2 * jp + 1]);
        Y2[jp] = pack2(ys[2 * jp], ys[2 * jp + 1]);
        Z2[jp] = pack2(zs[2 * jp], zs[2 * jp + 1]);
    }
    if (t == 0) { g_cent[b * SS] = 0; sidx[0] = 0x7fffffff; sidx[1] = 0x7fffffff; }
    int far = 0, par = 0;
    __syncthreads();

    for (int it = 1; it < SS; ++it) {
        float cx = sx[far], cy = sy[far], cz = sz[far];
        unsigned long long cx2 = pack2(-cx, -cx);
        unsigned long long cy2 = pack2(-cy, -cy);
        unsigned long long cz2 = pack2(-cz, -cz);
        float mf = 0.0f;                               // distances are >= 0
#pragma unroll
        for (int jp = 0; jp < 4; jp++) {
            unsigned long long dx2 = add2(X2[jp], cx2);
            unsigned long long dy2 = add2(Y2[jp], cy2);
            unsigned long long dz2 = add2(Z2[jp], cz2);
            unsigned long long d2 = fma2(dz2, dz2, fma2(dy2, dy2, mul2(dx2, dx2)));
            float dlo, dhi;
            unpack2(d2, dlo, dhi);
            float nlo = fminf(Dst[2 * jp], dlo);
            float nhi = fminf(Dst[2 * jp + 1], dhi);
            Dst[2 * jp] = nlo;
            Dst[2 * jp + 1] = nhi;
            mf = fmaxf(fmaxf(mf, nlo), nhi);
        }
        unsigned mb = __float_as_uint(mf);
        unsigned mw = __reduce_max_sync(0xffffffffu, mb);
        if (lane == 0) wmax[par][w] = mw;
        if (t == 0) sidx[par ^ 1] = 0x7fffffff;
        __syncthreads();
        unsigned M = __reduce_max_sync(0xffffffffu, wmax[par][lane]);
        if (mb == M) {
#pragma unroll
            for (int j = 0; j < 8; j++)
                if (__float_as_uint(Dst[j]) == M) { atomicMin(&sidx[par], j * 1024 + t); break; }
        }
        __syncthreads();
        far = sidx[par];
        if (t == 0) {
            g_cent[b * SS + it] = far;
            if ((it & 31) == 31) { __threadfence(); atomicExch(&g_prog[b], it); }
        }
        par ^= 1;
    }
}

// ================= role: ball query (bids 16..527) =================
// 32 warps = 32 centroids per block. Spin-waits on fps progress.
__device__ __forceinline__ void bq_role(const float* __restrict__ xyz,
                                        const float* __restrict__ points,
                                        float* __restrict__ out_newxyz,
                                        float4* sp, int idx)
{
    int g = idx >> 4, b = idx & 15;
    int t = threadIdx.x, warp = t >> 5, lane = t & 31;
    int s = (g << 5) + warp;

    if (t == 0) {
        while (atomicAdd(&g_prog[b], 0) < (g << 5) + 31) __nanosleep(256);
        __threadfence();
    }
    __syncthreads();

    int cidx = g_cent[b * SS + s];
    const float* cp = xyz + ((size_t)b * NN + cidx) * 3;
    float cx = cp[0], cy = cp[1], cz = cp[2];
    float cn2 = fmaf(cz, cz, fmaf(cy, cy, __fmul_rn(cx, cx)));
    if (lane < 3) out_newxyz[(b * SS + s) * 3 + lane] = cp[lane];

    const float R2 = 0.04f;
    float dl = 3.4e38f;
    int   il = 0;

    for (int tile = 0; tile < 4; ++tile) {
        __syncthreads();
        for (int i = t; i < 2048; i += 1024) {
            int gp = tile * 2048 + i;
            const float* pp = xyz + ((size_t)b * NN + gp) * 3;
            float px = pp[0], py = pp[1], pz = pp[2];
            sp[i] = make_float4(px, py, pz, fmaf(pz, pz, fmaf(py, py, __fmul_rn(px, px))));
        }
        __syncthreads();
        for (int chunk = 0; chunk < 64; ++chunk) {
            float4 p = sp[chunk * 32 + lane];
            float dot = fmaf(cz, p.z, fmaf(cy, p.y, __fmul_rn(cx, p.x)));
            float d   = __fsub_rn(__fadd_rn(cn2, p.w), __fmul_rn(2.0f, dot));
            float d31 = __shfl_sync(0xffffffffu, dl, 31);
            unsigned mask = __ballot_sync(0xffffffffu, d <= R2 && d < d31);
            while (mask) {
                int c0 = __ffs(mask) - 1;
                mask &= mask - 1;
                float dc = __shfl_sync(0xffffffffu, d, c0);
                d31 = __shfl_sync(0xffffffffu, dl, 31);
                if (dc < d31) {
                    int pos = __popc(__ballot_sync(0xffffffffu, dl <= dc));
                    float dprev = __shfl_up_sync(0xffffffffu, dl, 1);
                    int   iprev = __shfl_up_sync(0xffffffffu, il, 1);
                    int ic = tile * 2048 + chunk * 32 + c0;
                    if (lane >= pos) {
                        dl = (lane == pos) ? dc : dprev;
                        il = (lane == pos) ? ic : iprev;
                    }
                }
            }
        }
    }

    int first = __shfl_sync(0xffffffffu, il, 0);
    int gi = (dl > R2) ? first : il;
    const float* pr = points + ((size_t)b * NN + gi) * DD;
    int m0 = (b * SS + s) * KK;
    float v[DD];
#pragma unroll
    for (int c = 0; c < DD; c++) v[c] = pr[c];
#pragma unroll
    for (int c = 0; c < DD; c++)
        g_X0[(size_t)c * MCOL + m0 + lane] = v[c];

    // publish completion
    __syncthreads();
    if (t == 0) { __threadfence(); atomicExch(&g_flag[idx], 1); }
}

// ================= role: gemm0 9->64 (bids 528..1551) =================
// 1024 threads, 512-col tile (16 centroids). Waits on the covering bq block's flag.
__device__ __forceinline__ void gemm0_role(const float* __restrict__ W,
                                           const float* __restrict__ Bv,
                                           float* smf, int idx)
{
    float* WsT2 = smf;                    // [9][64][2]
    float* Xs   = WsT2 + 9 * 64 * 2;      // [9][512]
    float* sps  = Xs + 9 * 512;           // [2][64]
    float* spq  = sps + 128;              // [2][64]

    int t = threadIdx.x;
    int cb = idx >> 4, b = idx & 15;

    // load weights while waiting (no dependency)
    for (int i = t; i < 9 * 64; i += 1024) {
        int k = i >> 6, r = i & 63;
        float wv = W[r * 9 + k];
        WsT2[2 * i] = wv;
        WsT2[2 * i + 1] = wv;
    }
    if (t == 0) {
        while (atomicAdd(&g_flag[(cb >> 1) * 16 + b], 0) == 0) __nanosleep(256);
        __threadfence();
    }
    __syncthreads();

    size_t col0 = (size_t)b * 32768 + (size_t)cb * 512;
    for (int i = t; i < 9 * 512; i += 1024) {
        int c = i >> 9, x = i & 511;
        Xs[i] = g_X0[(size_t)c * MCOL + col0 + x];
    }
    __syncthreads();

    int cg = t & 63, rg = t >> 6;         // 64 col-groups x 16 row-groups
    unsigned long long acc[4][4];
#pragma unroll
    for (int r = 0; r < 4; r++)
#pragma unroll
        for (int c = 0; c < 4; c++) acc[r][c] = 0ull;

    const ulonglong2* Xs2 = reinterpret_cast<const ulonglong2*>(Xs);
    const unsigned long long* Wd = reinterpret_cast<const unsigned long long*>(WsT2);
#pragma unroll
    for (int k = 0; k < 9; k++) {
        ulonglong2 xa = Xs2[k * 128 + cg * 2];
        ulonglong2 xb = Xs2[k * 128 + cg * 2 + 1];
        unsigned long long xs4[4] = {xa.x, xa.y, xb.x, xb.y};
#pragma unroll
        for (int rr = 0; rr < 4; rr++) {
            unsigned long long w2 = Wd[k * 64 + rg * 4 + rr];
#pragma unroll
            for (int c = 0; c < 4; c++)
                acc[rr][c] = fma2(w2, xs4[c], acc[rr][c]);
        }
    }

    int lane = t & 31, half = (t >> 5) & 1;
#pragma unroll
    for (int rr = 0; rr < 4; rr++) {
        int r = rg * 4 + rr;
        float bb = Bv[r];
        float y[8];
#pragma unroll
        for (int c = 0; c < 4; c++) {
            float a, b2;
            unpack2(acc[rr][c], a, b2);
            y[2 * c]     = a + bb;
            y[2 * c + 1] = b2 + bb;
        }
        *reinterpret_cast<float4*>(g_Y0 + (size_t)r * MCOL + col0 + cg * 8) =
            make_float4(y[0], y[1], y[2], y[3]);
        *reinterpret_cast<float4*>(g_Y0 + (size_t)r * MCOL + col0 + cg * 8 + 4) =
            make_float4(y[4], y[5], y[6], y[7]);
        float ps = ((y[0] + y[1]) + (y[2] + y[3])) + ((y[4] + y[5]) + (y[6] + y[7]));
        float pq = ((y[0]*y[0] + y[1]*y[1]) + (y[2]*y[2] + y[3]*y[3]))
                 + ((y[4]*y[4] + y[5]*y[5]) + (y[6]*y[6] + y[7]*y[7]));
#pragma unroll
        for (int o = 16; o > 0; o >>= 1) {
            ps += __shfl_xor_sync(0xffffffffu, ps, o);
            pq += __shfl_xor_sync(0xffffffffu, pq, o);
        }
        if (lane == 0) { sps[half * 64 + r] = ps; spq[half * 64 + r] = pq; }
    }
    __syncthreads();
    if (t < 64) {
        g_ps [(size_t)t * NBLKMAX + idx] = (double)sps[t] + (double)sps[64 + t];
        g_pss[(size_t)t * NBLKMAX + idx] = (double)spq[t] + (double)spq[64 + t];
    }
}

// ================= fused pipeline kernel =================
__global__ __launch_bounds__(1024, 1) void fused_kernel(const float* __restrict__ xyz,
                                                        const float* __restrict__ points,
                                                        float* __restrict__ out_newxyz,
                                                        const float* __restrict__ W0,
                                                        const float* __restrict__ b0)
{
    extern __shared__ float smf[];
    int bid = blockIdx.x;
    if (bid < 16)        fps_role(xyz, smf, bid);
    else if (bid < 528)  bq_role(xyz, points, out_newxyz, reinterpret_cast<float4*>(smf), bid - 16);
    else                 gemm0_role(W0, b0, smf, bid - 528);
}

// ---------------- GEMM layers 1/2 (FFMA2, duplicated-W smem); POOL fuses maxpool ----------
template<int CIN, int COUT, int LAYER, bool POOL>
__global__ __launch_bounds__(256) void gemm_kernel(const float* __restrict__ X,
                                                   float* __restrict__ Y,
                                                   const float* __restrict__ W,
                                                   const float* __restrict__ Bv)
{
    constexpr int R = COUT / 16;
    extern __shared__ float sm[];
    float* WsT2 = sm;                    // [CIN][COUT][2]
    float* Xs   = WsT2 + CIN * COUT * 2; // [CIN][128]
    float* ssum = Xs  + CIN * 128;
    float* sss  = ssum + COUT;

    int t = threadIdx.x;
    size_t col0 = (size_t)blockIdx.x * 128;

    for (int i = t; i < CIN * COUT; i += 256) {
        int k = i / COUT, r = i - k * COUT;
        float wv = W[r * CIN + k];
        WsT2[2 * i] = wv;
        WsT2[2 * i + 1] = wv;
    }
    for (int i = t; i < CIN * 128; i += 256) {
        int c = i >> 7, x = i & 127;
        float v = X[(size_t)c * MCOL + col0 + x];
        v = fmaxf(fmaf(g_scl[LAYER - 1][c], v, g_shf[LAYER - 1][c]), 0.0f);
        Xs[i] = v;
    }
    __syncthreads();

    int cg = t & 15, rg = t >> 4;
    unsigned long long acc[R][4];
#pragma unroll
    for (int r = 0; r < R; r++)
#pragma unroll
        for (int c = 0; c < 4; c++) acc[r][c] = 0ull;

    const ulonglong2* Xs2 = reinterpret_cast<const ulonglong2*>(Xs);
    const unsigned long long* Wd = reinterpret_cast<const unsigned long long*>(WsT2);
#pragma unroll
    for (int k = 0; k < CIN; k++) {
        ulonglong2 xa = Xs2[k * 32 + cg * 2];
        ulonglong2 xb = Xs2[k * 32 + cg * 2 + 1];
        unsigned long long xs4[4] = {xa.x, xa.y, xb.x, xb.y};
#pragma unroll
        for (int rr = 0; rr < R; rr++) {
            unsigned long long w2 = Wd[k * COUT + rg * R + rr];
#pragma unroll
            for (int c = 0; c < 4; c++)
                acc[rr][c] = fma2(w2, xs4[c], acc[rr][c]);
        }
    }

    int lane = t & 31;
#pragma unroll
    for (int rr = 0; rr < R; rr++) {
        int r = rg * R + rr;
        float bb = Bv[r];
        float y[8];
#pragma unroll
        for (int c = 0; c < 4; c++) {
            float a, b2;
            unpack2(acc[rr][c], a, b2);
            y[2 * c]     = a + bb;
            y[2 * c + 1] = b2 + bb;
        }
        if (!POOL) {
            *reinterpret_cast<float4*>(Y + (size_t)r * MCOL + col0 + cg * 8) =
                make_float4(y[0], y[1], y[2], y[3]);
            *reinterpret_cast<float4*>(Y + (size_t)r * MCOL + col0 + cg * 8 + 4) =
                make_float4(y[4], y[5], y[6], y[7]);
        } else {
            float pm = y[0];
#pragma unroll
            for (int c = 1; c < 8; c++) pm = fmaxf(pm, y[c]);
            pm = fmaxf(pm, __shfl_xor_sync(0xffffffffu, pm, 1));
            pm = fmaxf(pm, __shfl_xor_sync(0xffffffffu, pm, 2));
            if ((cg & 3) == 0)
                g_P2[((size_t)blockIdx.x * 4 + (cg >> 2)) * 128 + r] = pm;
        }
        float ps = ((y[0] + y[1]) + (y[2] + y[3])) + ((y[4] + y[5]) + (y[6] + y[7]));
        float pq = ((y[0]*y[0] + y[1]*y[1]) + (y[2]*y[2] + y[3]*y[3]))
                 + ((y[4]*y[4] + y[5]*y[5]) + (y[6]*y[6] + y[7]*y[7]));
#pragma unroll
        for (int o = 8; o > 0; o >>= 1) {
            ps += __shfl_xor_sync(0xffffffffu, ps, o);
            pq += __shfl_xor_sync(0xffffffffu, pq, o);
        }
        if ((lane & 15) == 0) { ssum[r] = ps; sss[r] = pq; }
    }
    __syncthreads();
    if (t < COUT) {
        g_ps [(size_t)t * NBLKMAX + blockIdx.x] = (double)ssum[t];
        g_pss[(size_t)t * NBLKMAX + blockIdx.x] = (double)sss[t];
    }
}

// ---------------- BN finalize ----------------
__global__ __launch_bounds__(128) void finalize_kernel(const float* __restrict__ gamma,
                                                       const float* __restrict__ beta,
                                                       int layer, int nblk)
{
    int c = blockIdx.x, t = threadIdx.x;
    __shared__ double sh1[128], sh2[128];
    double a = 0.0, q = 0.0;
    for (int i = t; i < nblk; i += 128) {
        a += g_ps [(size_t)c * NBLKMAX + i];
        q += g_pss[(size_t)c * NBLKMAX + i];
    }
    sh1[t] = a; sh2[t] = q;
    __syncthreads();
    for (int o = 64; o > 0; o >>= 1) {
        if (t < o) { sh1[t] += sh1[t + o]; sh2[t] += sh2[t + o]; }
        __syncthreads();
    }
    if (t == 0) {
        double n = (double)MCOL;
        double mean = sh1[0] / n;
        double var  = sh2[0] / n - mean * mean;
        float sc = gamma[c] * rsqrtf((float)var + 1e-5f);
        g_scl[layer][c] = sc;
        g_shf[layer][c] = beta[c] - (float)mean * sc;
    }
}

// ---------------- final: BN2 affine + relu on pooled values ----------------
__global__ __launch_bounds__(256) void final_kernel(float* __restrict__ out)
{
    int g = blockIdx.x * 256 + threadIdx.x;
    int c = g & 127;
    out[g] = fmaxf(fmaf(g_scl[2][c], g_P2[g], g_shf[2][c]), 0.0f);
}

// ---------------- launch ----------------
extern "C" void kernel_launch(void* const* d_in, const int* in_sizes, int n_in,
                              void* d_out, int out_size)
{
    const float* xyz    = (const float*)d_in[0];
    const float* points = (const float*)d_in[1];
    const float* W0 = (const float*)d_in[2];
    const float* b0 = (const float*)d_in[3];
    const float* g0 = (const float*)d_in[4];
    const float* be0 = (const float*)d_in[5];
    const float* W1 = (const float*)d_in[6];
    const float* b1 = (const float*)d_in[7];
    const float* g1 = (const float*)d_in[8];
    const float* be1 = (const float*)d_in[9];
    const float* W2 = (const float*)d_in[10];
    const float* b2 = (const float*)d_in[11];
    const float* g2 = (const float*)d_in[12];
    const float* be2 = (const float*)d_in[13];

    float* out      = (float*)d_out;
    float* out_feat = out + BB * SS * 3;

    float *pY0, *pY1;
    cudaGetSymbolAddress((void**)&pY0, g_Y0);
    cudaGetSymbolAddress((void**)&pY1, g_Y1);

    // 2 pads: ncu capture slot (#4) = fused_kernel (after reset #3)
    for (int i = 0; i < 2; i++) pad_kernel<<<1, 32>>>();

    // reset pipeline progress flags (fresh each graph replay)
    reset_kernel<<<1, 512>>>();

    // fused fps + ballquery + gemm0 pipeline (1 block/SM via 120KB smem)
    const int FUSED_SMEM = 120 * 1024;
    cudaFuncSetAttribute(fused_kernel, cudaFuncAttributeMaxDynamicSharedMemorySize, FUSED_SMEM);
    fused_kernel<<<16 + 512 + NBLK0, 1024, FUSED_SMEM>>>(xyz, points, out, W0, b0);
    finalize_kernel<<<64, 128>>>(g0, be0, 0, NBLK0);

    // layer 1: 64 -> 64 (applies BN0+relu on input)
    {
        size_t smem = (size_t)(64 * 64 * 2 + 64 * 128 + 2 * 64) * 4;
        cudaFuncSetAttribute(gemm_kernel<64, 64, 1, false>, cudaFuncAttributeMaxDynamicSharedMemorySize, (int)smem);
        gemm_kernel<64, 64, 1, false><<<NBLK1, 256, smem>>>(pY0, pY1, W1, b1);
        finalize_kernel<<<64, 128>>>(g1, be1, 1, NBLK1);
    }
    // layer 2: 64 -> 128, maxpool fused
    {
        size_t smem = (size_t)(64 * 128 * 2 + 64 * 128 + 2 * 128) * 4;
        cudaFuncSetAttribute(gemm_kernel<64, 128, 2, true>, cudaFuncAttributeMaxDynamicSharedMemorySize, (int)smem);
        gemm_kernel<64, 128, 2, true><<<NBLK1, 256, smem>>>(pY1, pY0 /*unused*/, W2, b2);
        finalize_kernel<<<128, 128>>>(g2, be2, 2, NBLK1);
    }
    // BN2 affine + relu on pooled values -> feature output
    final_kernel<<<(BB * SS * 128) / 256, 256>>>(out_feat);
}

// round 8
// speedup vs baseline: 1.5200x; 1.5200x over previous
#include <cuda_runtime.h>
#include <cstddef>

#define BB   16
#define NN   8192
#define SS   1024        // NPOINT
#define KK   32          // NSAMPLE
#define DD   9
#define MCOL (BB*SS*KK)  // 524288 columns
#define NBLKMAX 4096     // g_ps leading stride
#define NBLK1 4096       // gemm1/2 blocks (128-wide tiles)
#define NBLK0 2048       // merged bq+gemm0 blocks (256-col tiles)

// ---------------- device scratch (static: no cudaMalloc allowed) ----------------
__device__ float  g_Y0[(size_t)64  * MCOL];   // layer0 raw out
__device__ float  g_Y1[(size_t)64  * MCOL];   // layer1 raw out
__device__ float  g_P2[(size_t)BB * SS * 128];// layer2 pooled raw max  [ms][c]
__device__ int    g_cent[BB * SS];
__device__ double g_ps [(size_t)128 * NBLKMAX];
__device__ double g_pss[(size_t)128 * NBLKMAX];
__device__ float  g_scl[3][128];
__device__ float  g_shf[3][128];

// ---------------- f32x2 packed helpers (sm_100+) ----------------
__device__ __forceinline__ unsigned long long pack2(float a, float b) {
    unsigned long long r;
    asm("mov.b64 %0, {%1, %2};" : "=l"(r) : "f"(a), "f"(b));
    return r;
}
__device__ __forceinline__ void unpack2(unsigned long long v, float& a, float& b) {
    asm("mov.b64 {%0, %1}, %2;" : "=f"(a), "=f"(b) : "l"(v));
}
__device__ __forceinline__ unsigned long long add2(unsigned long long a, unsigned long long b) {
    unsigned long long r;
    asm("add.rn.f32x2 %0, %1, %2;" : "=l"(r) : "l"(a), "l"(b));
    return r;
}
__device__ __forceinline__ unsigned long long mul2(unsigned long long a, unsigned long long b) {
    unsigned long long r;
    asm("mul.rn.f32x2 %0, %1, %2;" : "=l"(r) : "l"(a), "l"(b));
    return r;
}
__device__ __forceinline__ unsigned long long fma2(unsigned long long a, unsigned long long b, unsigned long long c) {
    unsigned long long r;
    asm("fma.rn.f32x2 %0, %1, %2, %3;" : "=l"(r) : "l"(a), "l"(b), "l"(c));
    return r;
}

// ---------------- pads: aim ncu capture slot (#4) at bqg0 ----------------
__global__ void pad_kernel() {}

// ---------------- FPS (R5-exact): f32x2 math + REDUX argmax ----------------
// d = fma(dz,dz, fma(dy,dy, dx*dx)) with dx = x + (-cx)  (== x - cx exactly)
__global__ __launch_bounds__(1024) void fps_kernel(const float* __restrict__ xyz)
{
    extern __shared__ float sh[];
    float* sx = sh;
    float* sy = sh + NN;
    float* sz = sh + 2 * NN;
    __shared__ unsigned bufv[2][32];
    __shared__ unsigned bufi[2][32];

    int b = blockIdx.x, t = threadIdx.x;
    int lane = t & 31, w = t >> 5;
    const float* xb = xyz + (size_t)b * NN * 3;

    float xs[8], ys[8], zs[8], Dst[8];
#pragma unroll
    for (int j = 0; j < 8; j++) {
        int p = j * 1024 + t;
        xs[j] = xb[p * 3 + 0];
        ys[j] = xb[p * 3 + 1];
        zs[j] = xb[p * 3 + 2];
        Dst[j] = 1e10f;
        sx[p] = xs[j]; sy[p] = ys[j]; sz[p] = zs[j];
    }
    unsigned long long X2[4], Y2[4], Z2[4];
#pragma unroll
    for (int jp = 0; jp < 4; jp++) {
        X2[jp] = pack2(xs[2 * jp], xs[2 * jp + 1]);
        Y2[jp] = pack2(ys[2 * jp], ys[2 * jp + 1]);
        Z2[jp] = pack2(zs[2 * jp], zs[2 * jp + 1]);
    }
    if (t == 0) g_cent[b * SS] = 0;
    int far = 0, par = 0;
    __syncthreads();

    for (int it = 1; it < SS; ++it) {
        float cx = sx[far], cy = sy[far], cz = sz[far];
        unsigned long long cx2 = pack2(-cx, -cx);
        unsigned long long cy2 = pack2(-cy, -cy);
        unsigned long long cz2 = pack2(-cz, -cz);
        float bv = -1.0f; int bi = 0;
#pragma unroll
        for (int jp = 0; jp < 4; jp++) {
            unsigned long long dx2 = add2(X2[jp], cx2);
            unsigned long long dy2 = add2(Y2[jp], cy2);
            unsigned long long dz2 = add2(Z2[jp], cz2);
            unsigned long long d2 = fma2(dz2, dz2, fma2(dy2, dy2, mul2(dx2, dx2)));
            float dlo, dhi;
            unpack2(d2, dlo, dhi);
            float nlo = fminf(Dst[2 * jp], dlo);
            float nhi = fminf(Dst[2 * jp + 1], dhi);
            Dst[2 * jp] = nlo;
            Dst[2 * jp + 1] = nhi;
            if (nlo > bv) { bv = nlo; bi = 2 * jp * 1024 + t; }       // ascending p
            if (nhi > bv) { bv = nhi; bi = (2 * jp + 1) * 1024 + t; } // strict > keeps first
        }
        // warp argmax via REDUX (d >= 0 so float bits are order-preserving)
        unsigned vb = __float_as_uint(bv);
        unsigned m1 = __reduce_max_sync(0xffffffffu, vb);
        unsigned c1 = (vb == m1) ? (unsigned)bi : 0xffffffffu;
        unsigned i1 = __reduce_min_sync(0xffffffffu, c1);
        if (lane == 0) { bufv[par][w] = m1; bufi[par][w] = i1; }
        __syncthreads();
        unsigned v2 = bufv[par][lane];
        unsigned i2 = bufi[par][lane];
        unsigned m2 = __reduce_max_sync(0xffffffffu, v2);
        unsigned c2 = (v2 == m2) ? i2 : 0xffffffffu;
        far = (int)__reduce_min_sync(0xffffffffu, c2);
        if (t == 0) g_cent[b * SS + it] = far;
        par ^= 1;
    }
}

// ---------------- Ball query + fused layer0 GEMM (9->64) ----------------
// Warp-per-centroid top-32; afterwards thread t owns output column (b*SS+s)*KK+lane.
// Layer0 applied in registers: y_r = (fma-chain over k of W0[r][k]*x[k]) + b0[r]
// -- bit-identical to the old standalone gemm0. Per-block BN partials via warp shfl.
__global__ __launch_bounds__(256) void bqg0_kernel(const float* __restrict__ xyz,
                                                   const float* __restrict__ points,
                                                   float* __restrict__ out_newxyz,
                                                   const float* __restrict__ W0,
                                                   const float* __restrict__ b0)
{
    __shared__ float4 sp[2048];
    __shared__ float sW[64 * 9];
    __shared__ float sB[64];
    __shared__ float swp[8][64];
    __shared__ float swq[8][64];

    int b    = blockIdx.x >> 7;                       // 128 blocks per batch
    int warp = threadIdx.x >> 5;
    int lane = threadIdx.x & 31;
    int t    = threadIdx.x;
    int s    = ((blockIdx.x & 127) << 3) + warp;      // centroid within batch

    // stage layer0 weights (ordered by first tile-loop barrier)
    for (int i = t; i < 576; i += 256) sW[i] = W0[i];
    if (t < 64) sB[t] = b0[t];

    int cidx = g_cent[b * SS + s];
    const float* cp = xyz + ((size_t)b * NN + cidx) * 3;
    float cx = cp[0], cy = cp[1], cz = cp[2];
    float cn2 = fmaf(cz, cz, fmaf(cy, cy, __fmul_rn(cx, cx)));
    if (lane < 3) out_newxyz[(b * SS + s) * 3 + lane] = cp[lane];

    const float R2 = 0.04f;   // float32 of radius**2
    float dl = 3.4e38f;       // rank-`lane` distance (sentinel = empty)
    int   il = 0;

    for (int tile = 0; tile < 4; ++tile) {
        __syncthreads();
        for (int i = t; i < 2048; i += 256) {
            int gp = tile * 2048 + i;
            const float* pp = xyz + ((size_t)b * NN + gp) * 3;
            float px = pp[0], py = pp[1], pz = pp[2];
            sp[i] = make_float4(px, py, pz, fmaf(pz, pz, fmaf(py, py, __fmul_rn(px, px))));
        }
        __syncthreads();
        for (int chunk = 0; chunk < 64; ++chunk) {
            float4 p = sp[chunk * 32 + lane];
            float dot = fmaf(cz, p.z, fmaf(cy, p.y, __fmul_rn(cx, p.x)));
            float d   = __fsub_rn(__fadd_rn(cn2, p.w), __fmul_rn(2.0f, dot));
            float d31 = __shfl_sync(0xffffffffu, dl, 31);
            unsigned mask = __ballot_sync(0xffffffffu, d <= R2 && d < d31);
            while (mask) {
                int c0 = __ffs(mask) - 1;             // ascending lane = ascending index
                mask &= mask - 1;
                float dc = __shfl_sync(0xffffffffu, d, c0);
                d31 = __shfl_sync(0xffffffffu, dl, 31);
                if (dc < d31) {                       // strict <: later equal never displaces
                    int pos = __popc(__ballot_sync(0xffffffffu, dl <= dc)); // after equals -> stable
                    float dprev = __shfl_up_sync(0xffffffffu, dl, 1);
                    int   iprev = __shfl_up_sync(0xffffffffu, il, 1);
                    int ic = tile * 2048 + chunk * 32 + c0;
                    if (lane >= pos) {
                        dl = (lane == pos) ? dc : dprev;
                        il = (lane == pos) ? ic : iprev;
                    }
                }
            }
        }
    }

    // radius replacement + gather of the 9 input channels (thread = one column)
    int first = __shfl_sync(0xffffffffu, il, 0);
    int gi = (dl > R2) ? first : il;
    const float* pr = points + ((size_t)b * NN + gi) * DD;
    float x[DD];
#pragma unroll
    for (int c = 0; c < DD; c++) x[c] = pr[c];

    // fused 9->64 layer: thread computes its column for all 64 channels
    size_t col = (size_t)(b * SS + ((blockIdx.x & 127) << 3)) * KK + t;
#pragma unroll 8
    for (int r = 0; r < 64; ++r) {
        float acc = 0.0f;
#pragma unroll
        for (int k = 0; k < DD; k++) acc = fmaf(sW[r * DD + k], x[k], acc);
        float y = acc + sB[r];
        g_Y0[(size_t)r * MCOL + col] = y;      // coalesced 1KB row-store per block
        float ps = y, pq = y * y;
#pragma unroll
        for (int o = 16; o > 0; o >>= 1) {
            ps += __shfl_xor_sync(0xffffffffu, ps, o);
            pq += __shfl_xor_sync(0xffffffffu, pq, o);
        }
        if (lane == 0) { swp[warp][r] = ps; swq[warp][r] = pq; }
    }
    __syncthreads();
    if (t < 64) {
        double a = 0.0, q = 0.0;
#pragma unroll
        for (int wv = 0; wv < 8; wv++) { a += (double)swp[wv][t]; q += (double)swq[wv][t]; }
        g_ps [(size_t)t * NBLKMAX + blockIdx.x] = a;
        g_pss[(size_t)t * NBLKMAX + blockIdx.x] = q;
    }
}

// ---------------- GEMM layers 1/2 (R5-exact FFMA2); POOL fuses maxpool ----------------
// 256 threads, tile = COUT rows x 128 cols. thread = R rows x 8 cols (4 f32x2 accs/row).
template<int CIN, int COUT, int LAYER, bool POOL>
__global__ __launch_bounds__(256) void gemm_kernel(const float* __restrict__ X,
                                                   float* __restrict__ Y,
                                                   const float* __restrict__ W,
                                                   const float* __restrict__ Bv)
{
    constexpr int R = COUT / 16;
    extern __shared__ float sm[];
    float* WsT  = sm;                    // [CIN][COUT] transposed weights
    float* Xs   = WsT + CIN * COUT;      // [CIN][128]
    float* ssum = Xs  + CIN * 128;       // [COUT]
    float* sss  = ssum + COUT;           // [COUT]

    int t = threadIdx.x;
    size_t col0 = (size_t)blockIdx.x * 128;

    for (int i = t; i < CIN * COUT; i += 256) {
        int k = i / COUT, r = i - k * COUT;
        WsT[i] = W[r * CIN + k];
    }
    for (int i = t; i < CIN * 128; i += 256) {
        int c = i >> 7, x = i & 127;
        float v = X[(size_t)c * MCOL + col0 + x];
        v = fmaxf(fmaf(g_scl[LAYER - 1][c], v, g_shf[LAYER - 1][c]), 0.0f);
        Xs[i] = v;
    }
    __syncthreads();

    int cg = t & 15, rg = t >> 4;
    unsigned long long acc[R][4];
#pragma unroll
    for (int r = 0; r < R; r++)
#pragma unroll
        for (int c = 0; c < 4; c++) acc[r][c] = 0ull;

    const ulonglong2* Xs2 = reinterpret_cast<const ulonglong2*>(Xs);
#pragma unroll
    for (int k = 0; k < CIN; k++) {
        ulonglong2 xa = Xs2[k * 32 + cg * 2];
        ulonglong2 xb = Xs2[k * 32 + cg * 2 + 1];
        unsigned long long xs4[4] = {xa.x, xa.y, xb.x, xb.y};
        const float4* Wr = reinterpret_cast<const float4*>(WsT + k * COUT + rg * R);
#pragma unroll
        for (int rr4 = 0; rr4 < R; rr4 += 4) {
            float4 wv = Wr[rr4 / 4];
            float wa[4] = {wv.x, wv.y, wv.z, wv.w};
#pragma unroll
            for (int q = 0; q < 4; q++) {
                unsigned long long w2 = pack2(wa[q], wa[q]);
#pragma unroll
                for (int c = 0; c < 4; c++)
                    acc[rr4 + q][c] = fma2(w2, xs4[c], acc[rr4 + q][c]);
            }
        }
    }

    int lane = t & 31;
#pragma unroll
    for (int rr = 0; rr < R; rr++) {
        int r = rg * R + rr;
        float bb = Bv[r];
        float y[8];
#pragma unroll
        for (int c = 0; c < 4; c++) {
            float a, b2;
            unpack2(acc[rr][c], a, b2);
            y[2 * c]     = a + bb;
            y[2 * c + 1] = b2 + bb;
        }
        if (!POOL) {
            *reinterpret_cast<float4*>(Y + (size_t)r * MCOL + col0 + cg * 8) =
                make_float4(y[0], y[1], y[2], y[3]);
            *reinterpret_cast<float4*>(Y + (size_t)r * MCOL + col0 + cg * 8 + 4) =
                make_float4(y[4], y[5], y[6], y[7]);
        } else {
            // raw-y max over this thread's 8 cols, then over the 4 cg-threads of the
            // 32-col group (affine with scale>0 and relu commute with max exactly)
            float pm = y[0];
#pragma unroll
            for (int c = 1; c < 8; c++) pm = fmaxf(pm, y[c]);
            pm = fmaxf(pm, __shfl_xor_sync(0xffffffffu, pm, 1));
            pm = fmaxf(pm, __shfl_xor_sync(0xffffffffu, pm, 2));
            if ((cg & 3) == 0)
                g_P2[((size_t)blockIdx.x * 4 + (cg >> 2)) * 128 + r] = pm;
        }
        float ps = ((y[0] + y[1]) + (y[2] + y[3])) + ((y[4] + y[5]) + (y[6] + y[7]));
        float pq = ((y[0]*y[0] + y[1]*y[1]) + (y[2]*y[2] + y[3]*y[3]))
                 + ((y[4]*y[4] + y[5]*y[5]) + (y[6]*y[6] + y[7]*y[7]));
#pragma unroll
        for (int o = 8; o > 0; o >>= 1) {
            ps += __shfl_xor_sync(0xffffffffu, ps, o);
            pq += __shfl_xor_sync(0xffffffffu, pq, o);
        }
        if ((lane & 15) == 0) { ssum[r] = ps; sss[r] = pq; }
    }
    __syncthreads();
    if (t < COUT) {
        g_ps [(size_t)t * NBLKMAX + blockIdx.x] = (double)ssum[t];
        g_pss[(size_t)t * NBLKMAX + blockIdx.x] = (double)sss[t];
    }
}

// ---------------- BN finalize: one block per channel, deterministic tree sum ----------------
__global__ __launch_bounds__(128) void finalize_kernel(const float* __restrict__ gamma,
                                                       const float* __restrict__ beta,
                                                       int layer, int nblk)
{
    int c = blockIdx.x, t = threadIdx.x;
    __shared__ double sh1[128], sh2[128];
    double a = 0.0, q = 0.0;
    for (int i = t; i < nblk; i += 128) {
        a += g_ps [(size_t)c * NBLKMAX + i];
        q += g_pss[(size_t)c * NBLKMAX + i];
    }
    sh1[t] = a; sh2[t] = q;
    __syncthreads();
    for (int o = 64; o > 0; o >>= 1) {
        if (t < o) { sh1[t] += sh1[t + o]; sh2[t] += sh2[t + o]; }
        __syncthreads();
    }
    if (t == 0) {
        double n = (double)MCOL;
        double mean = sh1[0] / n;
        double var  = sh2[0] / n - mean * mean;
        float sc = gamma[c] * rsqrtf((float)var + 1e-5f);
        g_scl[layer][c] = sc;
        g_shf[layer][c] = beta[c] - (float)mean * sc;
    }
}

// ---------------- final: BN2 affine + relu on pooled values (already [ms][c]) ----------------
__global__ __launch_bounds__(256) void final_kernel(float* __restrict__ out)
{
    int g = blockIdx.x * 256 + threadIdx.x;
    int c = g & 127;
    out[g] = fmaxf(fmaf(g_scl[2][c], g_P2[g], g_shf[2][c]), 0.0f);
}

// ---------------- launch ----------------
extern "C" void kernel_launch(void* const* d_in, const int* in_sizes, int n_in,
                              void* d_out, int out_size)
{
    const float* xyz    = (const float*)d_in[0];
    const float* points = (const float*)d_in[1];
    const float* W0 = (const float*)d_in[2];
    const float* b0 = (const float*)d_in[3];
    const float* g0 = (const float*)d_in[4];
    const float* be0 = (const float*)d_in[5];
    const float* W1 = (const float*)d_in[6];
    const float* b1 = (const float*)d_in[7];
    const float* g1 = (const float*)d_in[8];
    const float* be1 = (const float*)d_in[9];
    const float* W2 = (const float*)d_in[10];
    const float* b2 = (const float*)d_in[11];
    const float* g2 = (const float*)d_in[12];
    const float* be2 = (const float*)d_in[13];

    float* out      = (float*)d_out;
    float* out_feat = out + BB * SS * 3;

    float *pY0, *pY1;
    cudaGetSymbolAddress((void**)&pY0, g_Y0);
    cudaGetSymbolAddress((void**)&pY1, g_Y1);

    // 2 pads: ncu capture slot (#4) = bqg0_kernel
    for (int i = 0; i < 2; i++) pad_kernel<<<1, 32>>>();

    // FPS (96KB dynamic smem)
    cudaFuncSetAttribute(fps_kernel, cudaFuncAttributeMaxDynamicSharedMemorySize, 3 * NN * 4);
    fps_kernel<<<BB, 1024, 3 * NN * 4>>>(xyz);

    // ball query + fused layer0 (9->64) + new_xyz output
    bqg0_kernel<<<NBLK0, 256>>>(xyz, points, out, W0, b0);
    finalize_kernel<<<64, 128>>>(g0, be0, 0, NBLK0);

    // layer 1: 64 -> 64 (applies BN0+relu on input)
    {
        size_t smem = (size_t)(64 * 64 + 64 * 128 + 2 * 64) * 4;
        cudaFuncSetAttribute(gemm_kernel<64, 64, 1, false>, cudaFuncAttributeMaxDynamicSharedMemorySize, (int)smem);
        gemm_kernel<64, 64, 1, false><<<NBLK1, 256, smem>>>(pY0, pY1, W1, b1);
        finalize_kernel<<<64, 128>>>(g1, be1, 1, NBLK1);
    }
    // layer 2: 64 -> 128, maxpool fused (no Y2 materialization)
    {
        size_t smem = (size_t)(64 * 128 + 64 * 128 + 2 * 128) * 4;
        cudaFuncSetAttribute(gemm_kernel<64, 128, 2, true>, cudaFuncAttributeMaxDynamicSharedMemorySize, (int)smem);
        gemm_kernel<64, 128, 2, true><<<NBLK1, 256, smem>>>(pY1, pY0 /*unused*/, W2, b2);
        finalize_kernel<<<128, 128>>>(g2, be2, 2, NBLK1);
    }
    // BN2 affine + relu on pooled values -> feature output
    final_kernel<<<(BB * SS * 128) / 256, 256>>>(out_feat);
}